// round 10
// baseline (speedup 1.0000x reference)
#include <cuda_runtime.h>
#include <cstdint>

#define TT 256
#define HH 512
#define BB 128
#define NGATE 2048
#define GRID 128
#define NTHR 128
#define NKC 8
#define LDSD 136               // padded row stride (floats) -> conflict-free frags
#define CH_FL (128*LDSD)       // floats per full 128-row chunk  (17408)
#define STG_FL (64*LDSD)       // floats per CTA chunk slab      (8704)
#define STG_BY (STG_FL*4)      // 34816 B
#define SMEMB 118784           // 3 stages (104448) + pad -> forces 1 CTA/SM

#define O_H1F 16777216L
#define O_M0  16908288L
#define O_M1F 33685504L

// ---------------- device scratch ----------------
// W fragment order: f = [cell(2)][n0b(5)][kc(3)][wn4(1)][ks(4)][jj(1)][lane(5)][j2(1)][p(1)]
__device__ __align__(16) float g_Wf[8388608L];
__device__ __align__(16) float g_bias[4][NGATE];
// chunk-major padded A sources: [kc][m(128)][136]
__device__ __align__(16) float g_H0r[(long)TT*4*CH_FL];     // [t][kc][m][136]
__device__ __align__(16) float g_h1r[2][2][4*CH_FL];        // [layer][parity]
__device__ __align__(16) float g_h0ar[4*CH_FL];
__device__ __align__(16) float g_h0br[4*CH_FL];
// linear full-precision state
__device__ __align__(16) float g_h1f[2][BB*HH];
__device__ __align__(16) float g_m1[2][BB*HH];
__device__ __align__(16) float g_m0a[BB*HH];
// distributed barrier
__device__ volatile unsigned g_flag[GRID];
__device__ volatile unsigned g_gen;

// ---------------- helpers ----------------
__device__ __forceinline__ float tf32f(float x) {
    unsigned u; asm("cvt.rna.tf32.f32 %0, %1;" : "=r"(u) : "f"(x));
    return __uint_as_float(u);
}
__device__ __forceinline__ float sigf(float x) { return 1.f / (1.f + __expf(-x)); }

__device__ __forceinline__ void mma8(float* c, const unsigned* a, unsigned b0, unsigned b1) {
    asm volatile(
        "mma.sync.aligned.m16n8k8.row.col.f32.tf32.tf32.f32 "
        "{%0,%1,%2,%3}, {%4,%5,%6,%7}, {%8,%9}, {%0,%1,%2,%3};"
        : "+f"(c[0]), "+f"(c[1]), "+f"(c[2]), "+f"(c[3])
        : "r"(a[0]), "r"(a[1]), "r"(a[2]), "r"(a[3]), "r"(b0), "r"(b1));
}

__device__ __forceinline__ void mbwait(uint32_t mbar, unsigned par) {
    asm volatile(
        "{\n\t.reg .pred P;\n\t"
        "W%=:\n\t"
        "mbarrier.try_wait.parity.shared.b64 P, [%0], %1;\n\t"
        "@!P bra W%=;\n\t}"
        :: "r"(mbar), "r"(par) : "memory");
}

// one bulk copy: 64 rows x 136 floats (34816 B) -> smem stage  (tid 0 only)
__device__ __forceinline__ void ldbulk(uint32_t sb, uint32_t mb0, int st, int kc,
                                       const float* xq, const float* hq)
{
    const float* src = (kc < 4) ? (xq + (long)kc * CH_FL) : (hq + (long)(kc - 4) * CH_FL);
    uint32_t dst = sb + (uint32_t)st * STG_BY;
    uint32_t mb = mb0 + st * 8;
    asm volatile("mbarrier.arrive.expect_tx.shared.b64 _, [%0], %1;"
                 :: "r"(mb), "r"(STG_BY) : "memory");
    asm volatile("cp.async.bulk.shared::cluster.global.mbarrier::complete_tx::bytes "
                 "[%0], [%1], %2, [%3];"
                 :: "r"(dst), "l"(src), "r"(STG_BY), "r"(mb) : "memory");
}

// distributed-flag grid barrier: no atomics, monotonic phase counters.
// 128 CTAs all resident (1 CTA/SM via smem) -> deadlock-free.
__device__ __forceinline__ void gsync(int cta, unsigned ph1) {
    __threadfence();
    __syncthreads();
    int tid = threadIdx.x;
    if (cta == 0) {
        if (tid >= 1 && tid < GRID) {
            while (g_flag[tid] < ph1) { }    // each thread watches one CTA
        }
        __syncthreads();
        if (tid == 0) g_gen = ph1;
    } else {
        if (tid == 0) {
            g_flag[cta] = ph1;
            while (g_gen < ph1) { }
        }
    }
    __syncthreads();
    __threadfence();
}

// one LSTM cell tile: gates[64 x 64] = [x;h] @ W^T + b, then elementwise.
// 4 warps, warp tile 32m x 32n.
__device__ __noinline__ void cell_run(uint32_t sb, float* smf, uint32_t mb0, unsigned* mpar,
    int n0,
    const float* xq, const float* hq,
    const float* bias_n0,
    const float* cold,
    float* hfull, long hfs, float* hrd, float* cdst, long cds,
    const float* wbase)
{
    int tid = threadIdx.x, w = tid >> 5, lane = tid & 31;
    int rb = lane >> 2, q = lane & 3;
    int wm = (w & 1) * 32;
    int wn4 = w >> 1;            // 0..1
    int wn = wn4 * 32;

    float acc[2][4][4];          // [mfrag][nfrag][4]
    #pragma unroll
    for (int i = 0; i < 2; ++i)
        #pragma unroll
        for (int j = 0; j < 4; ++j)
            #pragma unroll
            for (int v = 0; v < 4; ++v) acc[i][j][v] = 0.f;

    float4 bA[4][2], bB[4][2];   // [s(4 ks)][jj]
    const float4* wl = (const float4*)wbase + wn4 * 1024 + lane;

    // W quarter loader: quarter qr (4 ks) of chunk kc -> buf (8 x LDG.128)
    #define LOADB(buf, kc_, qr_) do {                                          \
        const float4* wp_ = wl + (kc_) * 2048 + (qr_) * 256;                   \
        _Pragma("unroll")                                                      \
        for (int s_ = 0; s_ < 4; ++s_) {                                       \
            (buf)[s_][0] = wp_[s_ * 64];                                       \
            (buf)[s_][1] = wp_[s_ * 64 + 32];                                  \
        }                                                                      \
    } while (0)

    #define COMP4(buf, Ab_, qr_) do {                                          \
        const float* ap_ = (Ab_) + (wm + rb) * LDSD + 2 * q + (qr_) * 32;      \
        _Pragma("unroll")                                                      \
        for (int s_ = 0; s_ < 4; ++s_) {                                       \
            unsigned a_[2][4];                                                 \
            _Pragma("unroll")                                                  \
            for (int i_ = 0; i_ < 2; ++i_) {                                   \
                float2 lo_ = *(const float2*)(ap_ + i_ * 16 * LDSD + s_ * 8);  \
                float2 hi_ = *(const float2*)(ap_ + i_ * 16 * LDSD + 8 * LDSD + s_ * 8); \
                a_[i_][0] = __float_as_uint(lo_.x);                            \
                a_[i_][1] = __float_as_uint(hi_.x);                            \
                a_[i_][2] = __float_as_uint(lo_.y);                            \
                a_[i_][3] = __float_as_uint(hi_.y);                            \
            }                                                                  \
            float4 b0_ = (buf)[s_][0], b1_ = (buf)[s_][1];                     \
            _Pragma("unroll")                                                  \
            for (int i_ = 0; i_ < 2; ++i_) {                                   \
                mma8(acc[i_][0], a_[i_], __float_as_uint(b0_.x), __float_as_uint(b0_.y)); \
                mma8(acc[i_][1], a_[i_], __float_as_uint(b0_.z), __float_as_uint(b0_.w)); \
                mma8(acc[i_][2], a_[i_], __float_as_uint(b1_.x), __float_as_uint(b1_.y)); \
                mma8(acc[i_][3], a_[i_], __float_as_uint(b1_.z), __float_as_uint(b1_.w)); \
            }                                                                  \
        }                                                                      \
    } while (0)

    if (tid == 0) {
        ldbulk(sb, mb0, 0, 0, xq, hq);
        ldbulk(sb, mb0, 1, 1, xq, hq);
    }
    LOADB(bA, 0, 0);

    int st = 0;
    #pragma unroll 1
    for (int kc = 0; kc < NKC; ++kc) {
        __syncthreads();                         // all finished computing kc-1 (its stage now free)
        if (kc + 2 < NKC && tid == 0) {
            int s2 = st + 2; if (s2 >= 3) s2 -= 3;
            ldbulk(sb, mb0, s2, kc + 2, xq, hq);
        }
        mbwait(mb0 + st * 8, mpar[st] & 1);      // chunk kc data landed
        mpar[st]++;

        const float* Ab = smf + st * STG_FL;
        LOADB(bB, kc, 1);
        COMP4(bA, Ab, 0);
        LOADB(bA, kc, 2);
        COMP4(bB, Ab, 1);
        LOADB(bB, kc, 3);
        COMP4(bA, Ab, 2);
        if (kc + 1 < NKC) LOADB(bA, kc + 1, 0);
        COMP4(bB, Ab, 3);
        ++st; if (st >= 3) st -= 3;
    }
    #undef LOADB
    #undef COMP4

    // elementwise LSTM: gate cols 4u..4u+3 = (i,f,g,o) of unit u; pair lanes via shfl_xor 1
    bool ev = !(q & 1);
    #pragma unroll
    for (int i = 0; i < 2; ++i) {
        #pragma unroll
        for (int j = 0; j < 4; ++j) {
            int ncl = wn + 8 * j + 2 * q;
            float b0 = bias_n0[ncl];
            float b1 = bias_n0[ncl + 1];
            #pragma unroll
            for (int h = 0; h < 2; ++h) {
                float v0 = acc[i][j][2 * h] + b0;
                float v1 = acc[i][j][2 * h + 1] + b1;
                float p0 = __shfl_xor_sync(0xffffffffu, v0, 1);
                float p1 = __shfl_xor_sync(0xffffffffu, v1, 1);
                if (ev) {
                    float ig = v0, fg = v1, gg = p0, og = p1;
                    int mrow = wm + 16 * i + rb + 8 * h;   // 0..63 local
                    int u = (n0 + ncl) >> 2;                // 0..511
                    float co = cold ? __ldcg(cold + (long)mrow * HH + u) : 0.f;
                    float cn = sigf(fg) * co + sigf(ig) * tanhf(gg);
                    float hn = sigf(og) * tanhf(cn);
                    if (hfull) hfull[(long)mrow * hfs + u] = hn;
                    int ub = u & 7;
                    int up = (u & ~7) | ((ub < 4) ? 2 * ub : 2 * (ub - 4) + 1);  // forward k-permute
                    hrd[(long)(up >> 7) * CH_FL + (long)mrow * LDSD + (up & 127)] = tf32f(hn);
                    cdst[(long)mrow * cds + u] = cn;
                }
            }
        }
    }
}

// ---------------- main persistent kernel ----------------
__global__ void __launch_bounds__(NTHR, 1) lstm_main(float* __restrict__ out) {
    extern __shared__ __align__(16) float smf[];
    __shared__ __align__(8) unsigned long long s_mbar[3];
    uint32_t sb = (uint32_t)__cvta_generic_to_shared(smf);
    uint32_t mb0 = (uint32_t)__cvta_generic_to_shared(&s_mbar[0]);

    int tid = threadIdx.x;
    int cta = blockIdx.x;
    int grp = cta >> 6;
    int c = cta & 63;
    int m0 = (c & 1) * 64;
    int n0b = c >> 1;
    int n0 = n0b * 64;
    const long TH = (long)TT * HH;
    long mo136 = (long)m0 * LDSD;
    long moH = (long)m0 * HH;
    long moT = (long)m0 * TH;

    if (tid == 0) {
        #pragma unroll
        for (int s = 0; s < 3; ++s)
            asm volatile("mbarrier.init.shared.b64 [%0], 1;" :: "r"(mb0 + s * 8) : "memory");
    }
    __syncthreads();

    unsigned mpar[3] = {0, 0, 0};

    const float* w0 = g_Wf + ((long)(0 * 32 + n0b)) * 65536;
    const float* w1 = g_Wf + ((long)(1 * 32 + n0b)) * 65536;
    const float* w2 = g_Wf + ((long)(2 * 32 + n0b)) * 65536;
    const float* w3 = g_Wf + ((long)(3 * 32 + n0b)) * 65536;

    #pragma unroll 1
    for (int ph = 0; ph <= 2 * TT; ++ph) {
        int t = ph >> 1;
        if (!(ph & 1)) {
            if (grp == 0) {
                if (t < TT)   // cell00(t): x=h1r[0], h=H0r[:,t], c=0 -> h0ar,m0a
                    cell_run(sb, smf, mb0, mpar, n0,
                             g_h1r[0][t & 1] + mo136,
                             g_H0r + (long)t * 4 * CH_FL + mo136,
                             &g_bias[0][n0], nullptr,
                             nullptr, 0, g_h0ar + mo136, g_m0a + moH, HH, w0);
            } else if (t >= 1) {  // cell11(t-1): x=h0br, h=h1r[1], c=m1[1]
                int tp = t - 1;
                cell_run(sb, smf, mb0, mpar, n0,
                         g_h0br + mo136, g_h1r[1][tp & 1] + mo136,
                         &g_bias[3][n0], g_m1[1] + moH,
                         g_h1f[1] + moH, HH, g_h1r[1][(tp + 1) & 1] + mo136,
                         g_m1[1] + moH, HH, w3);
            }
        } else {
            if (grp == 0) {       // cell01(t): x=h0ar, h=h1r[0], c=m1[0]
                cell_run(sb, smf, mb0, mpar, n0,
                         g_h0ar + mo136, g_h1r[0][t & 1] + mo136,
                         &g_bias[1][n0], g_m1[0] + moH,
                         g_h1f[0] + moH, HH, g_h1r[0][(t + 1) & 1] + mo136,
                         g_m1[0] + moH, HH, w1);
            } else {              // cell10(t): x=h1r[1], h=h0ar, c=m0a -> d_out + h0br
                cell_run(sb, smf, mb0, mpar, n0,
                         g_h1r[1][t & 1] + mo136, g_h0ar + mo136,
                         &g_bias[2][n0], g_m0a + moH,
                         out + moT + (long)t * HH, TH, g_h0br + mo136,
                         out + O_M0 + moT + (long)t * HH, TH, w2);
            }
        }
        gsync(cta, (unsigned)(ph + 1));
    }

    // final H1f / M1f
    for (long idx = (long)cta * NTHR + tid; idx < 2L * BB * HH; idx += (long)GRID * NTHR) {
        int b = (int)(idx >> 10), l = (int)((idx >> 9) & 1), j = (int)(idx & 511);
        out[O_H1F + idx] = __ldcg(&g_h1f[l][b * HH + j]);
        out[O_M1F + idx] = __ldcg(&g_m1[l][b * HH + j]);
    }
}

// ---------------- prep kernels ----------------
// W fragment order: f = [cell(2)][n0b(5)][kc(3)][wn4(1)][ks(4)][jj(1)][lane(5)][j2(1)][p(1)]
__global__ void prep_wf(const float* __restrict__ Wih, const float* __restrict__ Whh) {
    long f = (long)blockIdx.x * blockDim.x + threadIdx.x;
    if (f >= 8388608L) return;
    int p    = (int)(f & 1);
    int j2   = (int)((f >> 1) & 1);
    int lane = (int)((f >> 2) & 31);
    int jj   = (int)((f >> 7) & 1);
    int ks   = (int)((f >> 8) & 15);
    int wn4  = (int)((f >> 12) & 1);
    int kc   = (int)((f >> 13) & 7);
    int n0b  = (int)((f >> 16) & 31);
    int cell = (int)(f >> 21);
    int rb = lane >> 2, q = lane & 3;
    int j = jj * 2 + j2;                              // n-frag 0..3
    int row = n0b * 64 + wn4 * 32 + j * 8 + rb;       // gate-interleaved: row = 4*unit + gate
    int g = row & 3, uu = row >> 2;
    long srow = (long)cell * NGATE + g * HH + uu;
    int k = kc * 128 + ks * 8 + q + p * 4;            // original k index
    float v = (k < HH) ? Wih[srow * HH + k] : Whh[srow * HH + (k - HH)];
    unsigned u; asm("cvt.rna.tf32.f32 %0, %1;" : "=r"(u) : "f"(v));
    g_Wf[f] = __uint_as_float(u);
}

// H0 [B][T][H] -> g_H0r [t][kc][m][136], FORWARD k-permute scatter + tf32 round.
__global__ void prep_x(const float* __restrict__ H0) {
    long i = (long)blockIdx.x * blockDim.x + threadIdx.x;
    if (i >= (long)BB * TT * HH) return;
    int h = (int)(i & 511);
    int t = (int)((i >> 9) & 255);
    int b = (int)(i >> 17);
    int hb = h & 7;
    int hp = (h & ~7) | ((hb < 4) ? 2 * hb : 2 * (hb - 4) + 1);
    int kc = hp >> 7, col = hp & 127;
    unsigned u; asm("cvt.rna.tf32.f32 %0, %1;" : "=r"(u) : "f"(H0[i]));
    g_H0r[((long)t * 4 + kc) * CH_FL + (long)b * LDSD + col] = __uint_as_float(u);
}

__global__ void prep_misc(const float* __restrict__ bih, const float* __restrict__ bhh) {
    long i = (long)blockIdx.x * blockDim.x + threadIdx.x;
    if (i < 2L * 2 * 4 * CH_FL) ((float*)g_h1r)[i] = 0.f;
    if (i < 2L * BB * HH) { ((float*)g_h1f)[i] = 0.f; ((float*)g_m1)[i] = 0.f; }
    if (i < 4 * NGATE) {
        int nr = (int)(i & 2047), cc = (int)(i >> 11);
        int g = nr & 3, j = nr >> 2;
        long s = (long)cc * NGATE + g * HH + j;
        ((float*)g_bias)[i] = bih[s] + bhh[s];
    }
    if (i < GRID) g_flag[i] = 0;
    if (i == 0) g_gen = 0;
}

// ---------------- launch ----------------
extern "C" void kernel_launch(void* const* d_in, const int* in_sizes, int n_in,
                              void* d_out, int out_size) {
    const float* H0  = (const float*)d_in[0];
    const float* Wih = (const float*)d_in[1];
    const float* Whh = (const float*)d_in[2];
    const float* bih = (const float*)d_in[3];
    const float* bhh = (const float*)d_in[4];
    float* out = (float*)d_out;

    prep_wf<<<32768, 256>>>(Wih, Whh);
    prep_x<<<65536, 256>>>(H0);
    prep_misc<<<2176, 256>>>(bih, bhh);

    cudaFuncSetAttribute(lstm_main, cudaFuncAttributeMaxDynamicSharedMemorySize, SMEMB);
    lstm_main<<<GRID, NTHR, SMEMB>>>(out);
}

// round 11
// speedup vs baseline: 1.0135x; 1.0135x over previous
#include <cuda_runtime.h>
#include <cstdint>

#define TT 256
#define HH 512
#define BB 128
#define NGATE 2048
#define GRID 128
#define NTHR 512
#define NKC 8
#define LDSD 136               // padded row stride (floats) -> conflict-free frags
#define CH_FL (128*LDSD)       // floats per full 128-row chunk  (17408)
#define STG_FL (64*LDSD)       // floats per CTA chunk slab      (8704)
#define STG_BY (STG_FL*4)      // 34816 B
#define SMEMB 118784           // 3 stages (104448) + pad -> forces 1 CTA/SM

#define O_H1F 16777216L
#define O_M0  16908288L
#define O_M1F 33685504L

// ---------------- device scratch ----------------
// W fragment order: f = [cell(2)][n0b(5)][kc(3)][wn4(2)][ks(4)][lane(5)][j(1)][p(1)]
__device__ __align__(16) float g_Wf[8388608L];
__device__ __align__(16) float g_bias[4][NGATE];
// chunk-major padded A sources: [kc][m(128)][136]
__device__ __align__(16) float g_H0r[(long)TT*4*CH_FL];     // [t][kc][m][136]
__device__ __align__(16) float g_h1r[2][2][4*CH_FL];        // [layer][parity]
__device__ __align__(16) float g_h0ar[4*CH_FL];
__device__ __align__(16) float g_h0br[4*CH_FL];
// linear full-precision state
__device__ __align__(16) float g_h1f[2][BB*HH];
__device__ __align__(16) float g_m1[2][BB*HH];
__device__ __align__(16) float g_m0a[BB*HH];
// distributed barrier
__device__ volatile unsigned g_flag[GRID];
__device__ volatile unsigned g_gen;

// ---------------- helpers ----------------
__device__ __forceinline__ float tf32f(float x) {
    unsigned u; asm("cvt.rna.tf32.f32 %0, %1;" : "=r"(u) : "f"(x));
    return __uint_as_float(u);
}
// fast sigmoid / tanh via ex2.approx + rcp.approx (rel err ~2^-21, inf-safe)
__device__ __forceinline__ float sigf(float x) {
    return __fdividef(1.f, 1.f + __expf(-x));
}
__device__ __forceinline__ float tanhfast(float x) {
    return 1.f - __fdividef(2.f, __expf(2.f * x) + 1.f);
}

__device__ __forceinline__ void mma8(float* c, const unsigned* a, unsigned b0, unsigned b1) {
    asm volatile(
        "mma.sync.aligned.m16n8k8.row.col.f32.tf32.tf32.f32 "
        "{%0,%1,%2,%3}, {%4,%5,%6,%7}, {%8,%9}, {%0,%1,%2,%3};"
        : "+f"(c[0]), "+f"(c[1]), "+f"(c[2]), "+f"(c[3])
        : "r"(a[0]), "r"(a[1]), "r"(a[2]), "r"(a[3]), "r"(b0), "r"(b1));
}

__device__ __forceinline__ void mbwait(uint32_t mbar, unsigned par) {
    asm volatile(
        "{\n\t.reg .pred P;\n\t"
        "W%=:\n\t"
        "mbarrier.try_wait.parity.shared.b64 P, [%0], %1;\n\t"
        "@!P bra W%=;\n\t}"
        :: "r"(mbar), "r"(par) : "memory");
}

// one bulk copy: 64 rows x 136 floats (34816 B) -> smem stage  (tid 0 only)
__device__ __forceinline__ void ldbulk(uint32_t sb, uint32_t mb0, int st, int kc,
                                       const float* xq, const float* hq)
{
    const float* src = (kc < 4) ? (xq + (long)kc * CH_FL) : (hq + (long)(kc - 4) * CH_FL);
    uint32_t dst = sb + (uint32_t)st * STG_BY;
    uint32_t mb = mb0 + st * 8;
    asm volatile("mbarrier.arrive.expect_tx.shared.b64 _, [%0], %1;"
                 :: "r"(mb), "r"(STG_BY) : "memory");
    asm volatile("cp.async.bulk.shared::cluster.global.mbarrier::complete_tx::bytes "
                 "[%0], [%1], %2, [%3];"
                 :: "r"(dst), "l"(src), "r"(STG_BY), "r"(mb) : "memory");
}

// distributed-flag grid barrier: no atomics, monotonic phase counters.
// 128 CTAs all resident (1 CTA/SM via smem) -> deadlock-free.
__device__ __forceinline__ void gsync(int cta, unsigned ph1) {
    __threadfence();
    __syncthreads();
    int tid = threadIdx.x;
    if (cta == 0) {
        if (tid >= 1 && tid < GRID) {
            while (g_flag[tid] < ph1) { }    // each thread watches one CTA
        }
        __syncthreads();
        if (tid == 0) g_gen = ph1;
    } else {
        if (tid == 0) {
            g_flag[cta] = ph1;
            while (g_gen < ph1) { }
        }
    }
    __syncthreads();
    __threadfence();
}

// one LSTM cell tile: gates[64 x 64] = [x;h] @ W^T + b, then elementwise.
// 16 warps, warp tile 16m x 16n.
__device__ __noinline__ void cell_run(uint32_t sb, float* smf, uint32_t mb0, unsigned* mpar,
    int n0,
    const float* xq, const float* hq,
    const float* bias_n0,
    const float* cold,
    float* hfull, long hfs, float* hrd, float* cdst, long cds,
    const float* wbase)
{
    int tid = threadIdx.x, w = tid >> 5, lane = tid & 31;
    int rb = lane >> 2, q = lane & 3;
    int wm = (w & 3) * 16;
    int wn4 = w >> 2;
    int wn = wn4 * 16;

    float acc[2][4];
    #pragma unroll
    for (int j = 0; j < 2; ++j)
        #pragma unroll
        for (int v = 0; v < 4; ++v) acc[j][v] = 0.f;

    float4 bA[8], bB[8];
    const float4* wlane4 = (const float4*)wbase + wn4 * 512 + lane;

    // W half-chunk loader: half h of chunk kc -> buf (8 x LDG.128)
    #define LOADB(buf, kc_, h_) do {                                           \
        const float4* wp_ = wlane4 + (kc_) * 2048;                             \
        _Pragma("unroll")                                                      \
        for (int ks_ = 0; ks_ < 8; ++ks_)                                      \
            (buf)[ks_] = wp_[(((h_) * 8 + ks_)) * 32];                         \
    } while (0)

    #define COMP8(buf, Ab_, ksb_) do {                                         \
        const float* ap_ = (Ab_) + (wm + rb) * LDSD + 2 * q + (ksb_) * 8;      \
        _Pragma("unroll")                                                      \
        for (int ks_ = 0; ks_ < 8; ++ks_) {                                    \
            unsigned a_[4];                                                    \
            float2 lo_ = *(const float2*)(ap_ + ks_ * 8);                      \
            float2 hi_ = *(const float2*)(ap_ + 8 * LDSD + ks_ * 8);           \
            a_[0] = __float_as_uint(lo_.x);                                    \
            a_[1] = __float_as_uint(hi_.x);                                    \
            a_[2] = __float_as_uint(lo_.y);                                    \
            a_[3] = __float_as_uint(hi_.y);                                    \
            float4 bv_ = (buf)[ks_];                                           \
            mma8(acc[0], a_, __float_as_uint(bv_.x), __float_as_uint(bv_.y));  \
            mma8(acc[1], a_, __float_as_uint(bv_.z), __float_as_uint(bv_.w));  \
        }                                                                      \
    } while (0)

    if (tid == 0) {
        ldbulk(sb, mb0, 0, 0, xq, hq);
        ldbulk(sb, mb0, 1, 1, xq, hq);
    }
    LOADB(bA, 0, 0);

    int st = 0;
    #pragma unroll 1
    for (int kc = 0; kc < NKC; ++kc) {
        __syncthreads();                         // all finished computing kc-1 (its stage now free)
        if (kc + 2 < NKC && tid == 0) {
            int s2 = st + 2; if (s2 >= 3) s2 -= 3;
            ldbulk(sb, mb0, s2, kc + 2, xq, hq);
        }
        mbwait(mb0 + st * 8, mpar[st] & 1);      // chunk kc data landed
        mpar[st]++;

        const float* Ab = smf + st * STG_FL;
        LOADB(bB, kc, 1);                        // prefetch 2nd half of this chunk's W
        COMP8(bA, Ab, 0);
        if (kc + 1 < NKC) LOADB(bA, kc + 1, 0);  // prefetch 1st half of next chunk's W
        COMP8(bB, Ab, 8);
        ++st; if (st >= 3) st -= 3;
    }
    #undef LOADB
    #undef COMP8

    // elementwise LSTM, both-lane version.
    // Pair (even q, odd q) holds one unit's 4 gate cols: even lane = (i,f), odd = (g,o),
    // rows rb (acc[.][0,1]) and rb+8 (acc[.][2,3]).
    // Even lane processes row rb, odd lane processes row rb+8 -> no idle lanes.
    bool ev = !(q & 1);
    #pragma unroll
    for (int j = 0; j < 2; ++j) {
        int lb = wn + 8 * j + ((q >> 1) << 2);     // unit base col (local), mult of 4
        float4 bb = *(const float4*)(bias_n0 + lb); // (b_i, b_f, b_g, b_o)
        float s0 = ev ? acc[j][2] : acc[j][0];
        float s1 = ev ? acc[j][3] : acc[j][1];
        float p0 = __shfl_xor_sync(0xffffffffu, s0, 1);
        float p1 = __shfl_xor_sync(0xffffffffu, s1, 1);
        float ig = (ev ? acc[j][0] : p0) + bb.x;
        float fg = (ev ? acc[j][1] : p1) + bb.y;
        float gg = (ev ? p0 : acc[j][2]) + bb.z;
        float og = (ev ? p1 : acc[j][3]) + bb.w;
        int mrow = wm + rb + (ev ? 0 : 8);          // 0..63 local
        int u = (n0 + lb) >> 2;                     // global unit 0..511
        float co = cold ? __ldcg(cold + (long)mrow * HH + u) : 0.f;
        float cn = sigf(fg) * co + sigf(ig) * tanhfast(gg);
        float hn = sigf(og) * tanhfast(cn);
        if (hfull) hfull[(long)mrow * hfs + u] = hn;
        int ub = u & 7;
        int up = (u & ~7) | ((ub < 4) ? 2 * ub : 2 * (ub - 4) + 1);  // forward k-permute
        hrd[(long)(up >> 7) * CH_FL + (long)mrow * LDSD + (up & 127)] = tf32f(hn);
        cdst[(long)mrow * cds + u] = cn;
    }
}

// ---------------- main persistent kernel ----------------
__global__ void __launch_bounds__(NTHR, 1) lstm_main(float* __restrict__ out) {
    extern __shared__ __align__(16) float smf[];
    __shared__ __align__(8) unsigned long long s_mbar[3];
    uint32_t sb = (uint32_t)__cvta_generic_to_shared(smf);
    uint32_t mb0 = (uint32_t)__cvta_generic_to_shared(&s_mbar[0]);

    int tid = threadIdx.x;
    int cta = blockIdx.x;
    int grp = cta >> 6;
    int c = cta & 63;
    int m0 = (c & 1) * 64;
    int n0b = c >> 1;
    int n0 = n0b * 64;
    const long TH = (long)TT * HH;
    long mo136 = (long)m0 * LDSD;
    long moH = (long)m0 * HH;
    long moT = (long)m0 * TH;

    if (tid == 0) {
        #pragma unroll
        for (int s = 0; s < 3; ++s)
            asm volatile("mbarrier.init.shared.b64 [%0], 1;" :: "r"(mb0 + s * 8) : "memory");
    }
    __syncthreads();

    unsigned mpar[3] = {0, 0, 0};

    const float* w0 = g_Wf + ((long)(0 * 32 + n0b)) * 65536;
    const float* w1 = g_Wf + ((long)(1 * 32 + n0b)) * 65536;
    const float* w2 = g_Wf + ((long)(2 * 32 + n0b)) * 65536;
    const float* w3 = g_Wf + ((long)(3 * 32 + n0b)) * 65536;

    #pragma unroll 1
    for (int ph = 0; ph <= 2 * TT; ++ph) {
        int t = ph >> 1;
        if (!(ph & 1)) {
            if (grp == 0) {
                if (t < TT)   // cell00(t): x=h1r[0], h=H0r[:,t], c=0 -> h0ar,m0a
                    cell_run(sb, smf, mb0, mpar, n0,
                             g_h1r[0][t & 1] + mo136,
                             g_H0r + (long)t * 4 * CH_FL + mo136,
                             &g_bias[0][n0], nullptr,
                             nullptr, 0, g_h0ar + mo136, g_m0a + moH, HH, w0);
            } else if (t >= 1) {  // cell11(t-1): x=h0br, h=h1r[1], c=m1[1]
                int tp = t - 1;
                cell_run(sb, smf, mb0, mpar, n0,
                         g_h0br + mo136, g_h1r[1][tp & 1] + mo136,
                         &g_bias[3][n0], g_m1[1] + moH,
                         g_h1f[1] + moH, HH, g_h1r[1][(tp + 1) & 1] + mo136,
                         g_m1[1] + moH, HH, w3);
            }
        } else {
            if (grp == 0) {       // cell01(t): x=h0ar, h=h1r[0], c=m1[0]
                cell_run(sb, smf, mb0, mpar, n0,
                         g_h0ar + mo136, g_h1r[0][t & 1] + mo136,
                         &g_bias[1][n0], g_m1[0] + moH,
                         g_h1f[0] + moH, HH, g_h1r[0][(t + 1) & 1] + mo136,
                         g_m1[0] + moH, HH, w1);
            } else {              // cell10(t): x=h1r[1], h=h0ar, c=m0a -> d_out + h0br
                cell_run(sb, smf, mb0, mpar, n0,
                         g_h1r[1][t & 1] + mo136, g_h0ar + mo136,
                         &g_bias[2][n0], g_m0a + moH,
                         out + moT + (long)t * HH, TH, g_h0br + mo136,
                         out + O_M0 + moT + (long)t * HH, TH, w2);
            }
        }
        gsync(cta, (unsigned)(ph + 1));
    }

    // final H1f / M1f
    for (long idx = (long)cta * NTHR + tid; idx < 2L * BB * HH; idx += (long)GRID * NTHR) {
        int b = (int)(idx >> 10), l = (int)((idx >> 9) & 1), j = (int)(idx & 511);
        out[O_H1F + idx] = __ldcg(&g_h1f[l][b * HH + j]);
        out[O_M1F + idx] = __ldcg(&g_m1[l][b * HH + j]);
    }
}

// ---------------- prep kernels ----------------
// W fragment order: f = [cell(2)][n0b(5)][kc(3)][wn4(2)][ks(4)][lane(5)][j(1)][p(1)]
__global__ void prep_wf(const float* __restrict__ Wih, const float* __restrict__ Whh) {
    long f = (long)blockIdx.x * blockDim.x + threadIdx.x;
    if (f >= 8388608L) return;
    int p    = (int)(f & 1);
    int j    = (int)((f >> 1) & 1);
    int lane = (int)((f >> 2) & 31);
    int ks   = (int)((f >> 7) & 15);
    int wn4  = (int)((f >> 11) & 3);
    int kc   = (int)((f >> 13) & 7);
    int n0b  = (int)((f >> 16) & 31);
    int cell = (int)(f >> 21);
    int rb = lane >> 2, q = lane & 3;
    int row = n0b * 64 + wn4 * 16 + j * 8 + rb;      // gate-interleaved: row = 4*unit + gate
    int g = row & 3, jj = row >> 2;
    long srow = (long)cell * NGATE + g * HH + jj;
    int k = kc * 128 + ks * 8 + q + p * 4;            // original k index
    float v = (k < HH) ? Wih[srow * HH + k] : Whh[srow * HH + (k - HH)];
    unsigned u; asm("cvt.rna.tf32.f32 %0, %1;" : "=r"(u) : "f"(v));
    g_Wf[f] = __uint_as_float(u);
}

// H0 [B][T][H] -> g_H0r [t][kc][m][136], FORWARD k-permute scatter + tf32 round.
__global__ void prep_x(const float* __restrict__ H0) {
    long i = (long)blockIdx.x * blockDim.x + threadIdx.x;
    if (i >= (long)BB * TT * HH) return;
    int h = (int)(i & 511);
    int t = (int)((i >> 9) & 255);
    int b = (int)(i >> 17);
    int hb = h & 7;
    int hp = (h & ~7) | ((hb < 4) ? 2 * hb : 2 * (hb - 4) + 1);
    int kc = hp >> 7, col = hp & 127;
    unsigned u; asm("cvt.rna.tf32.f32 %0, %1;" : "=r"(u) : "f"(H0[i]));
    g_H0r[((long)t * 4 + kc) * CH_FL + (long)b * LDSD + col] = __uint_as_float(u);
}

__global__ void prep_misc(const float* __restrict__ bih, const float* __restrict__ bhh) {
    long i = (long)blockIdx.x * blockDim.x + threadIdx.x;
    if (i < 2L * 2 * 4 * CH_FL) ((float*)g_h1r)[i] = 0.f;
    if (i < 2L * BB * HH) { ((float*)g_h1f)[i] = 0.f; ((float*)g_m1)[i] = 0.f; }
    if (i < 4 * NGATE) {
        int nr = (int)(i & 2047), cc = (int)(i >> 11);
        int g = nr & 3, j = nr >> 2;
        long s = (long)cc * NGATE + g * HH + j;
        ((float*)g_bias)[i] = bih[s] + bhh[s];
    }
    if (i < GRID) g_flag[i] = 0;
    if (i == 0) g_gen = 0;
}

// ---------------- launch ----------------
extern "C" void kernel_launch(void* const* d_in, const int* in_sizes, int n_in,
                              void* d_out, int out_size) {
    const float* H0  = (const float*)d_in[0];
    const float* Wih = (const float*)d_in[1];
    const float* Whh = (const float*)d_in[2];
    const float* bih = (const float*)d_in[3];
    const float* bhh = (const float*)d_in[4];
    float* out = (float*)d_out;

    prep_wf<<<32768, 256>>>(Wih, Whh);
    prep_x<<<65536, 256>>>(H0);
    prep_misc<<<2176, 256>>>(bih, bhh);

    cudaFuncSetAttribute(lstm_main, cudaFuncAttributeMaxDynamicSharedMemorySize, SMEMB);
    lstm_main<<<GRID, NTHR, SMEMB>>>(out);
}

// round 12
// speedup vs baseline: 1.0415x; 1.0276x over previous
#include <cuda_runtime.h>
#include <cstdint>

#define TT 256
#define HH 512
#define BB 128
#define NGATE 2048
#define GRID 128
#define NTHR 512
#define NKC 8
#define LDSD 136               // padded row stride (floats) -> conflict-free frags
#define CH_FL (128*LDSD)       // floats per full 128-row chunk  (17408)
#define STG_FL (64*LDSD)       // floats per CTA chunk slab      (8704)
#define STG_BY (STG_FL*4)      // 34816 B
#define SMEMB 118784           // 3 stages (104448) + pad -> forces 1 CTA/SM

#define O_H1F 16777216L
#define O_M0  16908288L
#define O_M1F 33685504L

// ---------------- device scratch ----------------
// W fragment order: f = [cell(2)][n0b(5)][kc(3)][wn4(2)][ks(4)][lane(5)][j(1)][p(1)]
__device__ __align__(16) float g_Wf[8388608L];
__device__ __align__(16) float g_bias[4][NGATE];
// chunk-major padded A sources: [kc][m(128)][136]
__device__ __align__(16) float g_H0r[(long)TT*4*CH_FL];     // [t][kc][m][136]
__device__ __align__(16) float g_h1r[2][2][4*CH_FL];        // [layer][parity]
__device__ __align__(16) float g_h0ar[2][4*CH_FL];          // [t-parity] c00 h-out
__device__ __align__(16) float g_h0br[4*CH_FL];             // c10 h-out scratch
// linear full-precision state
__device__ __align__(16) float g_h1f[2][BB*HH];
__device__ __align__(16) float g_m1[2][BB*HH];
__device__ __align__(16) float g_m0a[2][BB*HH];             // [t-parity] c00 c-out
// per-group barriers + cross-group progress
__device__ unsigned g_cnt0, g_cnt1;
__device__ volatile unsigned g_gen0, g_gen1;
__device__ volatile unsigned g_prog0, g_prog0b, g_prog1, g_prog1b;

// ---------------- helpers ----------------
__device__ __forceinline__ float tf32f(float x) {
    unsigned u; asm("cvt.rna.tf32.f32 %0, %1;" : "=r"(u) : "f"(x));
    return __uint_as_float(u);
}
// fast sigmoid / tanh (rel err ~2^-21, inf-safe)
__device__ __forceinline__ float sigf(float x) {
    return __fdividef(1.f, 1.f + __expf(-x));
}
__device__ __forceinline__ float tanhfast(float x) {
    return 1.f - __fdividef(2.f, __expf(2.f * x) + 1.f);
}

__device__ __forceinline__ void mma8(float* c, const unsigned* a, unsigned b0, unsigned b1) {
    asm volatile(
        "mma.sync.aligned.m16n8k8.row.col.f32.tf32.tf32.f32 "
        "{%0,%1,%2,%3}, {%4,%5,%6,%7}, {%8,%9}, {%0,%1,%2,%3};"
        : "+f"(c[0]), "+f"(c[1]), "+f"(c[2]), "+f"(c[3])
        : "r"(a[0]), "r"(a[1]), "r"(a[2]), "r"(a[3]), "r"(b0), "r"(b1));
}

__device__ __forceinline__ void mbwait(uint32_t mbar, unsigned par) {
    asm volatile(
        "{\n\t.reg .pred P;\n\t"
        "W%=:\n\t"
        "mbarrier.try_wait.parity.shared.b64 P, [%0], %1;\n\t"
        "@!P bra W%=;\n\t}"
        :: "r"(mbar), "r"(par) : "memory");
}

// one bulk copy: 64 rows x 136 floats (34816 B) -> smem stage  (tid 0 only)
__device__ __forceinline__ void ldbulk(uint32_t sb, uint32_t mb0, int st, int kc,
                                       const float* xq, const float* hq)
{
    const float* src = (kc < 4) ? (xq + (long)kc * CH_FL) : (hq + (long)(kc - 4) * CH_FL);
    uint32_t dst = sb + (uint32_t)st * STG_BY;
    uint32_t mb = mb0 + st * 8;
    asm volatile("mbarrier.arrive.expect_tx.shared.b64 _, [%0], %1;"
                 :: "r"(mb), "r"(STG_BY) : "memory");
    asm volatile("cp.async.bulk.shared::cluster.global.mbarrier::complete_tx::bytes "
                 "[%0], [%1], %2, [%3];"
                 :: "r"(dst), "l"(src), "r"(STG_BY), "r"(mb) : "memory");
}

// 64-CTA group barrier (atomic arrival chain, proven in R9).
// Master optionally publishes a progress counter before release.
__device__ __forceinline__ void gbar(unsigned* cnt, volatile unsigned* gen,
                                     volatile unsigned* prog, unsigned pval) {
    __threadfence();
    __syncthreads();
    if (threadIdx.x == 0) {
        unsigned g = *gen;
        if (atomicAdd(cnt, 1u) == 63) {
            *cnt = 0;
            if (prog) *prog = pval;
            __threadfence();
            *gen = g + 1;
        } else {
            while (*gen == g) { }
        }
    }
    __syncthreads();
    __threadfence();
}

// per-CTA wait on a monotonic progress counter
__device__ __forceinline__ void waitctr(volatile unsigned* c, unsigned v) {
    __syncthreads();
    if (threadIdx.x == 0) {
        while (*c < v) { }
    }
    __syncthreads();
    __threadfence();
}

// one LSTM cell tile: gates[64 x 64] = [x;h] @ W^T + b, then elementwise.
// 16 warps, warp tile 16m x 16n.
__device__ __noinline__ void cell_run(uint32_t sb, float* smf, uint32_t mb0, unsigned* mpar,
    int n0,
    const float* xq, const float* hq,
    const float* bias_n0,
    const float* cold,
    float* hfull, long hfs, float* hrd, float* cdst, long cds,
    const float* wbase)
{
    int tid = threadIdx.x, w = tid >> 5, lane = tid & 31;
    int rb = lane >> 2, q = lane & 3;
    int wm = (w & 3) * 16;
    int wn4 = w >> 2;
    int wn = wn4 * 16;

    float acc[2][4];
    #pragma unroll
    for (int j = 0; j < 2; ++j)
        #pragma unroll
        for (int v = 0; v < 4; ++v) acc[j][v] = 0.f;

    float4 bA[8], bB[8];
    const float4* wlane4 = (const float4*)wbase + wn4 * 512 + lane;

    // W half-chunk loader: half h of chunk kc -> buf (8 x LDG.128)
    #define LOADB(buf, kc_, h_) do {                                           \
        const float4* wp_ = wlane4 + (kc_) * 2048;                             \
        _Pragma("unroll")                                                      \
        for (int ks_ = 0; ks_ < 8; ++ks_)                                      \
            (buf)[ks_] = wp_[(((h_) * 8 + ks_)) * 32];                         \
    } while (0)

    #define COMP8(buf, Ab_, ksb_) do {                                         \
        const float* ap_ = (Ab_) + (wm + rb) * LDSD + 2 * q + (ksb_) * 8;      \
        _Pragma("unroll")                                                      \
        for (int ks_ = 0; ks_ < 8; ++ks_) {                                    \
            unsigned a_[4];                                                    \
            float2 lo_ = *(const float2*)(ap_ + ks_ * 8);                      \
            float2 hi_ = *(const float2*)(ap_ + 8 * LDSD + ks_ * 8);           \
            a_[0] = __float_as_uint(lo_.x);                                    \
            a_[1] = __float_as_uint(hi_.x);                                    \
            a_[2] = __float_as_uint(lo_.y);                                    \
            a_[3] = __float_as_uint(hi_.y);                                    \
            float4 bv_ = (buf)[ks_];                                           \
            mma8(acc[0], a_, __float_as_uint(bv_.x), __float_as_uint(bv_.y));  \
            mma8(acc[1], a_, __float_as_uint(bv_.z), __float_as_uint(bv_.w));  \
        }                                                                      \
    } while (0)

    if (tid == 0) {
        ldbulk(sb, mb0, 0, 0, xq, hq);
        ldbulk(sb, mb0, 1, 1, xq, hq);
    }
    LOADB(bA, 0, 0);

    int st = 0;
    #pragma unroll 1
    for (int kc = 0; kc < NKC; ++kc) {
        __syncthreads();                         // all finished computing kc-1 (its stage now free)
        if (kc + 2 < NKC && tid == 0) {
            int s2 = st + 2; if (s2 >= 3) s2 -= 3;
            ldbulk(sb, mb0, s2, kc + 2, xq, hq);
        }
        mbwait(mb0 + st * 8, mpar[st] & 1);      // chunk kc data landed
        mpar[st]++;

        const float* Ab = smf + st * STG_FL;
        LOADB(bB, kc, 1);                        // prefetch 2nd half of this chunk's W
        COMP8(bA, Ab, 0);
        if (kc + 1 < NKC) LOADB(bA, kc + 1, 0);  // prefetch 1st half of next chunk's W
        COMP8(bB, Ab, 8);
        ++st; if (st >= 3) st -= 3;
    }
    #undef LOADB
    #undef COMP8

    // elementwise LSTM, both-lane version (no idle lanes).
    bool ev = !(q & 1);
    #pragma unroll
    for (int j = 0; j < 2; ++j) {
        int lb = wn + 8 * j + ((q >> 1) << 2);      // unit base col (local), mult of 4
        float4 bb = *(const float4*)(bias_n0 + lb); // (b_i, b_f, b_g, b_o)
        float s0 = ev ? acc[j][2] : acc[j][0];
        float s1 = ev ? acc[j][3] : acc[j][1];
        float p0 = __shfl_xor_sync(0xffffffffu, s0, 1);
        float p1 = __shfl_xor_sync(0xffffffffu, s1, 1);
        float ig = (ev ? acc[j][0] : p0) + bb.x;
        float fg = (ev ? acc[j][1] : p1) + bb.y;
        float gg = (ev ? p0 : acc[j][2]) + bb.z;
        float og = (ev ? p1 : acc[j][3]) + bb.w;
        int mrow = wm + rb + (ev ? 0 : 8);          // 0..63 local
        int u = (n0 + lb) >> 2;                     // global unit 0..511
        float co = cold ? __ldcg(cold + (long)mrow * HH + u) : 0.f;
        float cn = sigf(fg) * co + sigf(ig) * tanhfast(gg);
        float hn = sigf(og) * tanhfast(cn);
        if (hfull) hfull[(long)mrow * hfs + u] = hn;
        int ub = u & 7;
        int up = (u & ~7) | ((ub < 4) ? 2 * ub : 2 * (ub - 4) + 1);  // forward k-permute
        hrd[(long)(up >> 7) * CH_FL + (long)mrow * LDSD + (up & 127)] = tf32f(hn);
        cdst[(long)mrow * cds + u] = cn;
    }
}

// ---------------- main persistent kernel ----------------
__global__ void __launch_bounds__(NTHR, 1) lstm_main(float* __restrict__ out) {
    extern __shared__ __align__(16) float smf[];
    __shared__ __align__(8) unsigned long long s_mbar[3];
    uint32_t sb = (uint32_t)__cvta_generic_to_shared(smf);
    uint32_t mb0 = (uint32_t)__cvta_generic_to_shared(&s_mbar[0]);

    int tid = threadIdx.x;
    int cta = blockIdx.x;
    int grp = cta >> 6;
    int c = cta & 63;
    int m0 = (c & 1) * 64;
    int n0b = c >> 1;
    int n0 = n0b * 64;
    const long TH = (long)TT * HH;
    long mo136 = (long)m0 * LDSD;
    long moH = (long)m0 * HH;
    long moT = (long)m0 * TH;

    if (tid == 0) {
        #pragma unroll
        for (int s = 0; s < 3; ++s)
            asm volatile("mbarrier.init.shared.b64 [%0], 1;" :: "r"(mb0 + s * 8) : "memory");
    }
    __syncthreads();

    unsigned mpar[3] = {0, 0, 0};

    const float* w0 = g_Wf + ((long)(0 * 32 + n0b)) * 65536;
    const float* w1 = g_Wf + ((long)(1 * 32 + n0b)) * 65536;
    const float* w2 = g_Wf + ((long)(2 * 32 + n0b)) * 65536;
    const float* w3 = g_Wf + ((long)(3 * 32 + n0b)) * 65536;

    if (grp == 0) {
        // grp0 chain: c00(t) -> c01(t), 64-CTA barriers, runs up to 2 steps ahead of grp1
        #pragma unroll 1
        for (int t = 0; t < TT; ++t) {
            if (t >= 2) waitctr(&g_prog1, (unsigned)(t - 1));   // h0ar/m0a[t&1] free?
            // cell00(t): x=h1r[0][t&1], h=H0r[:,t], c=0 -> h0ar[t&1], m0a[t&1]
            cell_run(sb, smf, mb0, mpar, n0,
                     g_h1r[0][t & 1] + mo136,
                     g_H0r + (long)t * 4 * CH_FL + mo136,
                     &g_bias[0][n0], nullptr,
                     nullptr, 0, g_h0ar[t & 1] + mo136, g_m0a[t & 1] + moH, HH, w0);
            gbar(&g_cnt0, &g_gen0, &g_prog0, (unsigned)(t + 1));
            // cell01(t): x=h0ar[t&1], h=h1r[0][t&1], c=m1[0]
            cell_run(sb, smf, mb0, mpar, n0,
                     g_h0ar[t & 1] + mo136, g_h1r[0][t & 1] + mo136,
                     &g_bias[1][n0], g_m1[0] + moH,
                     g_h1f[0] + moH, HH, g_h1r[0][(t + 1) & 1] + mo136,
                     g_m1[0] + moH, HH, w1);
            gbar(&g_cnt0, &g_gen0, &g_prog0b, (unsigned)(t + 1));
        }
    } else {
        // grp1 chain: c10(t) -> c11(t), consumes grp0's h0ar/m0a via prog0
        #pragma unroll 1
        for (int t = 0; t < TT; ++t) {
            waitctr(&g_prog0, (unsigned)(t + 1));               // c00(t) done?
            // cell10(t): x=h1r[1][t&1], h=h0ar[t&1], c=m0a[t&1] -> d_out + h0br
            cell_run(sb, smf, mb0, mpar, n0,
                     g_h1r[1][t & 1] + mo136, g_h0ar[t & 1] + mo136,
                     &g_bias[2][n0], g_m0a[t & 1] + moH,
                     out + moT + (long)t * HH, TH, g_h0br + mo136,
                     out + O_M0 + moT + (long)t * HH, TH, w2);
            gbar(&g_cnt1, &g_gen1, &g_prog1, (unsigned)(t + 1));
            // cell11(t): x=h0br, h=h1r[1][t&1], c=m1[1]
            cell_run(sb, smf, mb0, mpar, n0,
                     g_h0br + mo136, g_h1r[1][t & 1] + mo136,
                     &g_bias[3][n0], g_m1[1] + moH,
                     g_h1f[1] + moH, HH, g_h1r[1][(t + 1) & 1] + mo136,
                     g_m1[1] + moH, HH, w3);
            gbar(&g_cnt1, &g_gen1, &g_prog1b, (unsigned)(t + 1));
        }
    }

    // final join: both chains complete
    waitctr(&g_prog0b, (unsigned)TT);
    waitctr(&g_prog1b, (unsigned)TT);

    // final H1f / M1f
    for (long idx = (long)cta * NTHR + tid; idx < 2L * BB * HH; idx += (long)GRID * NTHR) {
        int b = (int)(idx >> 10), l = (int)((idx >> 9) & 1), j = (int)(idx & 511);
        out[O_H1F + idx] = __ldcg(&g_h1f[l][b * HH + j]);
        out[O_M1F + idx] = __ldcg(&g_m1[l][b * HH + j]);
    }
}

// ---------------- prep kernels ----------------
// W fragment order: f = [cell(2)][n0b(5)][kc(3)][wn4(2)][ks(4)][lane(5)][j(1)][p(1)]
__global__ void prep_wf(const float* __restrict__ Wih, const float* __restrict__ Whh) {
    long f = (long)blockIdx.x * blockDim.x + threadIdx.x;
    if (f >= 8388608L) return;
    int p    = (int)(f & 1);
    int j    = (int)((f >> 1) & 1);
    int lane = (int)((f >> 2) & 31);
    int ks   = (int)((f >> 7) & 15);
    int wn4  = (int)((f >> 11) & 3);
    int kc   = (int)((f >> 13) & 7);
    int n0b  = (int)((f >> 16) & 31);
    int cell = (int)(f >> 21);
    int rb = lane >> 2, q = lane & 3;
    int row = n0b * 64 + wn4 * 16 + j * 8 + rb;      // gate-interleaved: row = 4*unit + gate
    int g = row & 3, jj = row >> 2;
    long srow = (long)cell * NGATE + g * HH + jj;
    int k = kc * 128 + ks * 8 + q + p * 4;            // original k index
    float v = (k < HH) ? Wih[srow * HH + k] : Whh[srow * HH + (k - HH)];
    unsigned u; asm("cvt.rna.tf32.f32 %0, %1;" : "=r"(u) : "f"(v));
    g_Wf[f] = __uint_as_float(u);
}

// H0 [B][T][H] -> g_H0r [t][kc][m][136], FORWARD k-permute scatter + tf32 round.
__global__ void prep_x(const float* __restrict__ H0) {
    long i = (long)blockIdx.x * blockDim.x + threadIdx.x;
    if (i >= (long)BB * TT * HH) return;
    int h = (int)(i & 511);
    int t = (int)((i >> 9) & 255);
    int b = (int)(i >> 17);
    int hb = h & 7;
    int hp = (h & ~7) | ((hb < 4) ? 2 * hb : 2 * (hb - 4) + 1);
    int kc = hp >> 7, col = hp & 127;
    unsigned u; asm("cvt.rna.tf32.f32 %0, %1;" : "=r"(u) : "f"(H0[i]));
    g_H0r[((long)t * 4 + kc) * CH_FL + (long)b * LDSD + col] = __uint_as_float(u);
}

__global__ void prep_misc(const float* __restrict__ bih, const float* __restrict__ bhh) {
    long i = (long)blockIdx.x * blockDim.x + threadIdx.x;
    if (i < 2L * 2 * 4 * CH_FL) ((float*)g_h1r)[i] = 0.f;
    if (i < 2L * BB * HH) { ((float*)g_h1f)[i] = 0.f; ((float*)g_m1)[i] = 0.f; }
    if (i < 4 * NGATE) {
        int nr = (int)(i & 2047), cc = (int)(i >> 11);
        int g = nr & 3, j = nr >> 2;
        long s = (long)cc * NGATE + g * HH + j;
        ((float*)g_bias)[i] = bih[s] + bhh[s];
    }
    if (i == 0) {
        g_cnt0 = 0; g_cnt1 = 0;
        g_gen0 = 0; g_gen1 = 0;
        g_prog0 = 0; g_prog0b = 0; g_prog1 = 0; g_prog1b = 0;
    }
}

// ---------------- launch ----------------
extern "C" void kernel_launch(void* const* d_in, const int* in_sizes, int n_in,
                              void* d_out, int out_size) {
    const float* H0  = (const float*)d_in[0];
    const float* Wih = (const float*)d_in[1];
    const float* Whh = (const float*)d_in[2];
    const float* bih = (const float*)d_in[3];
    const float* bhh = (const float*)d_in[4];
    float* out = (float*)d_out;

    prep_wf<<<32768, 256>>>(Wih, Whh);
    prep_x<<<65536, 256>>>(H0);
    prep_misc<<<2176, 256>>>(bih, bhh);

    cudaFuncSetAttribute(lstm_main, cudaFuncAttributeMaxDynamicSharedMemorySize, SMEMB);
    lstm_main<<<GRID, NTHR, SMEMB>>>(out);
}

// round 13
// speedup vs baseline: 1.3694x; 1.3149x over previous
#include <cuda_runtime.h>
#include <cuda_fp16.h>
#include <cstdint>

#define TT 256
#define HH 512
#define BB 128
#define NGATE 2048
#define GRID 128
#define NTHR 512
#define NKC 8
#define RSH 144                 // halves per padded row (288 B; 288%128=32 -> conflict-free)
#define CH_HF (128*RSH)         // halves per full 128-row chunk (18432)
#define HSLAB 9216              // halves per CTA half-chunk (64*RSH)
#define STG_BY 18432            // bytes per smem stage
#define SMEMB 118784            // 4 stages (73728) + pad -> forces 1 CTA/SM

#define O_H1F 16777216L
#define O_M0  16908288L
#define O_M1F 33685504L

// ---------------- device scratch ----------------
// W fp16 fragment order, float4 index fi4 = [cell(2)][n0b(5)][kc(3)][wn4(2)][ks(3)][lane(5)],
// halves within float4: j(1) r(1) hb(1)
__device__ __align__(16) __half g_Wf[8388608L];
__device__ __align__(16) float g_bias[4][NGATE];
// chunk-major padded fp16 A sources: [kc][m(128)][144]
__device__ __align__(16) __half g_H0r[(long)TT*4*CH_HF];
__device__ __align__(16) __half g_h1r[2][2][4*CH_HF];   // [layer][parity]
__device__ __align__(16) __half g_h0ar[4*CH_HF];
__device__ __align__(16) __half g_h0br[4*CH_HF];
// linear full-precision state
__device__ __align__(16) float g_h1f[2][BB*HH];
__device__ __align__(16) float g_m1[2][BB*HH];
__device__ __align__(16) float g_m0a[BB*HH];
__device__ unsigned g_cnt;
__device__ volatile unsigned g_gen;

// ---------------- helpers ----------------
__device__ __forceinline__ float sigf(float x) {
    return __fdividef(1.f, 1.f + __expf(-x));
}
__device__ __forceinline__ float tanhfast(float x) {
    return 1.f - __fdividef(2.f, __expf(2.f * x) + 1.f);
}

// fp16 mma: D(16x8) += A(16x16) B(16x8), fp32 accum
__device__ __forceinline__ void mma16(float* c, unsigned a0, unsigned a1, unsigned a2, unsigned a3,
                                      unsigned b0, unsigned b1) {
    asm volatile(
        "mma.sync.aligned.m16n8k16.row.col.f32.f16.f16.f32 "
        "{%0,%1,%2,%3}, {%4,%5,%6,%7}, {%8,%9}, {%0,%1,%2,%3};"
        : "+f"(c[0]), "+f"(c[1]), "+f"(c[2]), "+f"(c[3])
        : "r"(a0), "r"(a1), "r"(a2), "r"(a3), "r"(b0), "r"(b1));
}

__device__ __forceinline__ void mbwait(uint32_t mbar, unsigned par) {
    asm volatile(
        "{\n\t.reg .pred P;\n\t"
        "W%=:\n\t"
        "mbarrier.try_wait.parity.shared.b64 P, [%0], %1;\n\t"
        "@!P bra W%=;\n\t}"
        :: "r"(mbar), "r"(par) : "memory");
}

// one bulk copy: 64 rows x 144 halves (18432 B) -> smem stage (tid 0 only)
__device__ __forceinline__ void ldbulk(uint32_t sb, uint32_t mb0, int st, int kc,
                                       const __half* xq, const __half* hq)
{
    const __half* src = (kc < 4) ? (xq + (long)kc * CH_HF) : (hq + (long)(kc - 4) * CH_HF);
    uint32_t dst = sb + (uint32_t)st * STG_BY;
    uint32_t mb = mb0 + st * 8;
    asm volatile("mbarrier.arrive.expect_tx.shared.b64 _, [%0], %1;"
                 :: "r"(mb), "r"(STG_BY) : "memory");
    asm volatile("cp.async.bulk.shared::cluster.global.mbarrier::complete_tx::bytes "
                 "[%0], [%1], %2, [%3];"
                 :: "r"(dst), "l"(src), "r"(STG_BY), "r"(mb) : "memory");
}

// grid barrier (R9-proven atomic form): 128 CTAs, all resident -> deadlock-free
__device__ __forceinline__ void gsync() {
    __threadfence();
    __syncthreads();
    if (threadIdx.x == 0) {
        unsigned g = g_gen;
        if (atomicAdd(&g_cnt, 1u) == GRID - 1) {
            g_cnt = 0;
            __threadfence();
            g_gen = g + 1;
        } else {
            while (g_gen == g) { }
        }
    }
    __syncthreads();
    __threadfence();
}

// permuted half-offset within a slab for original k-feature u (0..511)
__device__ __forceinline__ long kpos(int u) {
    int kc2 = u >> 7, k2 = u & 127;
    int blk = k2 >> 4, kb = (k2 >> 1) & 7, hb = k2 & 1;
    int p = (kb < 4) ? (2 * kb) : (2 * (kb - 4) + 1);
    return (long)kc2 * CH_HF + blk * 16 + p * 2 + hb;
}

// one LSTM cell tile: gates[64 x 64] = [x;h] @ W^T + b, then elementwise.
// 16 warps, warp tile 16m x 16n, fp16 operands, fp32 accum.
__device__ __noinline__ void cell_run(uint32_t sb, char* smc, uint32_t mb0, unsigned* mpar,
    int n0,
    const __half* xq, const __half* hq,
    const float* bias_n0,
    const float* cold,
    float* hfull, long hfs, __half* hrd, float* cdst, long cds,
    const float4* wbase)
{
    int tid = threadIdx.x, w = tid >> 5, lane = tid & 31;
    int rb = lane >> 2, q = lane & 3;
    int wm = (w & 3) * 16;
    int wn4 = w >> 2;
    int wn = wn4 * 16;

    float acc[2][4];
    #pragma unroll
    for (int j = 0; j < 2; ++j)
        #pragma unroll
        for (int v = 0; v < 4; ++v) acc[j][v] = 0.f;

    float4 bA[4], bB[4];
    const float4* wl = wbase + wn4 * 256 + lane;

    // W loader: half h_ (4 k-steps) of chunk kc -> buf (4 x LDG.128)
    #define LOADB(buf, kc_, h_) do {                                           \
        const float4* wp_ = wl + (kc_) * 1024 + (h_) * 128;                    \
        _Pragma("unroll")                                                      \
        for (int s_ = 0; s_ < 4; ++s_)                                         \
            (buf)[s_] = wp_[s_ * 32];                                          \
    } while (0)

    // compute 4 k-steps (64 k) from A stage + reg W buf
    #define COMP4(buf, Ab_, qr_) do {                                          \
        const char* ap_ = (Ab_) + (wm + rb) * 288 + 8 * q + (qr_) * 128;       \
        _Pragma("unroll")                                                      \
        for (int s_ = 0; s_ < 4; ++s_) {                                       \
            uint2 lo_ = *(const uint2*)(ap_ + s_ * 32);                        \
            uint2 hi_ = *(const uint2*)(ap_ + 8 * 288 + s_ * 32);              \
            float4 bv_ = (buf)[s_];                                            \
            mma16(acc[0], lo_.x, hi_.x, lo_.y, hi_.y,                          \
                  __float_as_uint(bv_.x), __float_as_uint(bv_.y));             \
            mma16(acc[1], lo_.x, hi_.x, lo_.y, hi_.y,                          \
                  __float_as_uint(bv_.z), __float_as_uint(bv_.w));             \
        }                                                                      \
    } while (0)

    if (tid == 0) {
        ldbulk(sb, mb0, 0, 0, xq, hq);
        ldbulk(sb, mb0, 1, 1, xq, hq);
        ldbulk(sb, mb0, 2, 2, xq, hq);
    }
    LOADB(bA, 0, 0);

    int st = 0;
    #pragma unroll 1
    for (int kc = 0; kc < NKC; ++kc) {
        __syncthreads();                         // compute of kc-1 done -> stage (kc+3)&3 free
        if (kc + 3 < NKC && tid == 0) {
            ldbulk(sb, mb0, (kc + 3) & 3, kc + 3, xq, hq);
        }
        mbwait(mb0 + st * 8, mpar[st] & 1);      // chunk kc data landed
        mpar[st]++;

        char* Ab = smc + st * STG_BY;
        LOADB(bB, kc, 1);                        // prefetch 2nd half of this chunk's W
        COMP4(bA, Ab, 0);
        if (kc + 1 < NKC) LOADB(bA, kc + 1, 0);  // prefetch 1st half of next chunk's W
        COMP4(bB, Ab, 1);
        st = (st + 1) & 3;
    }
    #undef LOADB
    #undef COMP4

    // elementwise LSTM, both-lane version (no idle lanes).
    bool ev = !(q & 1);
    #pragma unroll
    for (int j = 0; j < 2; ++j) {
        int lb = wn + 8 * j + ((q >> 1) << 2);      // unit base col (local), mult of 4
        float4 bb = *(const float4*)(bias_n0 + lb); // (b_i, b_f, b_g, b_o)
        float s0 = ev ? acc[j][2] : acc[j][0];
        float s1 = ev ? acc[j][3] : acc[j][1];
        float p0 = __shfl_xor_sync(0xffffffffu, s0, 1);
        float p1 = __shfl_xor_sync(0xffffffffu, s1, 1);
        float ig = (ev ? acc[j][0] : p0) + bb.x;
        float fg = (ev ? acc[j][1] : p1) + bb.y;
        float gg = (ev ? p0 : acc[j][2]) + bb.z;
        float og = (ev ? p1 : acc[j][3]) + bb.w;
        int mrow = wm + rb + (ev ? 0 : 8);          // 0..63 local
        int u = (n0 + lb) >> 2;                     // global unit 0..511
        float co = cold ? __ldcg(cold + (long)mrow * HH + u) : 0.f;
        float cn = sigf(fg) * co + sigf(ig) * tanhfast(gg);
        float hn = sigf(og) * tanhfast(cn);
        if (hfull) hfull[(long)mrow * hfs + u] = hn;
        hrd[kpos(u) + (long)mrow * RSH] = __float2half_rn(hn);
        cdst[(long)mrow * cds + u] = cn;
    }
}

// ---------------- main persistent kernel ----------------
__global__ void __launch_bounds__(NTHR, 1) lstm_main(float* __restrict__ out) {
    extern __shared__ __align__(16) char smc[];
    __shared__ __align__(8) unsigned long long s_mbar[4];
    uint32_t sb = (uint32_t)__cvta_generic_to_shared(smc);
    uint32_t mb0 = (uint32_t)__cvta_generic_to_shared(&s_mbar[0]);

    int tid = threadIdx.x;
    int cta = blockIdx.x;
    int grp = cta >> 6;
    int c = cta & 63;
    int m0 = (c & 1) * 64;
    int n0b = c >> 1;
    int n0 = n0b * 64;
    const long TH = (long)TT * HH;
    long moS = (long)m0 * RSH;       // half-slab offset
    long moH = (long)m0 * HH;
    long moT = (long)m0 * TH;

    if (tid == 0) {
        #pragma unroll
        for (int s = 0; s < 4; ++s)
            asm volatile("mbarrier.init.shared.b64 [%0], 1;" :: "r"(mb0 + s * 8) : "memory");
    }
    __syncthreads();

    unsigned mpar[4] = {0, 0, 0, 0};

    const float4* w0 = (const float4*)g_Wf + ((long)(0 * 32 + n0b)) * 8192;
    const float4* w1 = (const float4*)g_Wf + ((long)(1 * 32 + n0b)) * 8192;
    const float4* w2 = (const float4*)g_Wf + ((long)(2 * 32 + n0b)) * 8192;
    const float4* w3 = (const float4*)g_Wf + ((long)(3 * 32 + n0b)) * 8192;

    #pragma unroll 1
    for (int ph = 0; ph <= 2 * TT; ++ph) {
        int t = ph >> 1;
        if (!(ph & 1)) {
            if (grp == 0) {
                if (t < TT)   // cell00(t): x=h1r[0][t&1], h=H0r[:,t], c=0 -> h0ar,m0a
                    cell_run(sb, smc, mb0, mpar, n0,
                             g_h1r[0][t & 1] + moS,
                             g_H0r + (long)t * 4 * CH_HF + moS,
                             &g_bias[0][n0], nullptr,
                             nullptr, 0, g_h0ar + moS, g_m0a + moH, HH, w0);
            } else if (t >= 1) {  // cell11(t-1): x=h0br, h=h1r[1], c=m1[1]
                int tp = t - 1;
                cell_run(sb, smc, mb0, mpar, n0,
                         g_h0br + moS, g_h1r[1][tp & 1] + moS,
                         &g_bias[3][n0], g_m1[1] + moH,
                         g_h1f[1] + moH, HH, g_h1r[1][(tp + 1) & 1] + moS,
                         g_m1[1] + moH, HH, w3);
            }
        } else {
            if (grp == 0) {       // cell01(t): x=h0ar, h=h1r[0], c=m1[0]
                cell_run(sb, smc, mb0, mpar, n0,
                         g_h0ar + moS, g_h1r[0][t & 1] + moS,
                         &g_bias[1][n0], g_m1[0] + moH,
                         g_h1f[0] + moH, HH, g_h1r[0][(t + 1) & 1] + moS,
                         g_m1[0] + moH, HH, w1);
            } else {              // cell10(t): x=h1r[1], h=h0ar, c=m0a -> d_out + h0br
                cell_run(sb, smc, mb0, mpar, n0,
                         g_h1r[1][t & 1] + moS, g_h0ar + moS,
                         &g_bias[2][n0], g_m0a + moH,
                         out + moT + (long)t * HH, TH, g_h0br + moS,
                         out + O_M0 + moT + (long)t * HH, TH, w2);
            }
        }
        gsync();
    }

    // final H1f / M1f
    for (long idx = (long)cta * NTHR + tid; idx < 2L * BB * HH; idx += (long)GRID * NTHR) {
        int b = (int)(idx >> 10), l = (int)((idx >> 9) & 1), j = (int)(idx & 511);
        out[O_H1F + idx] = __ldcg(&g_h1f[l][b * HH + j]);
        out[O_M1F + idx] = __ldcg(&g_m1[l][b * HH + j]);
    }
}

// ---------------- prep kernels ----------------
// W fp16 fragment order. Half index f bits (LSB up):
// hb(1) r(1) j(1) lane(5) ks(3) wn4(2) kc(3) n0b(5) cell(2)
__global__ void prep_wf(const float* __restrict__ Wih, const float* __restrict__ Whh) {
    long f = (long)blockIdx.x * blockDim.x + threadIdx.x;
    if (f >= 8388608L) return;
    int hb   = (int)(f & 1);
    int r    = (int)((f >> 1) & 1);
    int j    = (int)((f >> 2) & 1);
    int lane = (int)((f >> 3) & 31);
    int ks   = (int)((f >> 8) & 7);
    int wn4  = (int)((f >> 11) & 3);
    int kc   = (int)((f >> 13) & 7);
    int n0b  = (int)((f >> 16) & 31);
    int cell = (int)(f >> 21);
    int rb = lane >> 2, q = lane & 3;
    int row = n0b * 64 + wn4 * 16 + j * 8 + rb;      // gate-interleaved: row = 4*unit + gate
    int g = row & 3, uu = row >> 2;
    long srow = (long)cell * NGATE + g * HH + uu;
    int k = kc * 128 + ks * 16 + r * 8 + 2 * q + hb;  // original k index
    float v = (k < HH) ? Wih[srow * HH + k] : Whh[srow * HH + (k - HH)];
    g_Wf[f] = __float2half_rn(v);
}

// H0 [B][T][H] -> g_H0r [t][kc][m][144] fp16, pair-level FORWARD k-permute
__global__ void prep_x(const float* __restrict__ H0) {
    long i = (long)blockIdx.x * blockDim.x + threadIdx.x;
    if (i >= (long)BB * TT * HH) return;
    int h = (int)(i & 511);
    int t = (int)((i >> 9) & 255);
    int b = (int)(i >> 17);
    int kc = h >> 7, k2 = h & 127;
    int blk = k2 >> 4, kb = (k2 >> 1) & 7, hb = k2 & 1;
    int p = (kb < 4) ? (2 * kb) : (2 * (kb - 4) + 1);
    int col = blk * 16 + p * 2 + hb;
    g_H0r[((long)t * 4 + kc) * CH_HF + (long)b * RSH + col] = __float2half_rn(H0[i]);
}

__global__ void prep_misc(const float* __restrict__ bih, const float* __restrict__ bhh) {
    long i = (long)blockIdx.x * blockDim.x + threadIdx.x;
    if (i < 147456) ((int*)g_h1r)[i] = 0;                        // zero fp16 h1r slabs
    if (i < 2L * BB * HH) { ((float*)g_h1f)[i] = 0.f; ((float*)g_m1)[i] = 0.f; }
    if (i < 4 * NGATE) {
        int nr = (int)(i & 2047), cc = (int)(i >> 11);
        int g = nr & 3, j = nr >> 2;
        long s = (long)cc * NGATE + g * HH + j;
        ((float*)g_bias)[i] = bih[s] + bhh[s];
    }
    if (i == 0) { g_cnt = 0; g_gen = 0; }
}

// ---------------- launch ----------------
extern "C" void kernel_launch(void* const* d_in, const int* in_sizes, int n_in,
                              void* d_out, int out_size) {
    const float* H0  = (const float*)d_in[0];
    const float* Wih = (const float*)d_in[1];
    const float* Whh = (const float*)d_in[2];
    const float* bih = (const float*)d_in[3];
    const float* bhh = (const float*)d_in[4];
    float* out = (float*)d_out;

    prep_wf<<<32768, 256>>>(Wih, Whh);
    prep_x<<<65536, 256>>>(H0);
    prep_misc<<<1024, 256>>>(bih, bhh);

    cudaFuncSetAttribute(lstm_main, cudaFuncAttributeMaxDynamicSharedMemorySize, SMEMB);
    lstm_main<<<GRID, NTHR, SMEMB>>>(out);
}